// round 14
// baseline (speedup 1.0000x reference)
#include <cuda_runtime.h>
#include <cstdint>

#define T_LEN 8192
#define NLAG  64

// x buffer: 64 chunks of 128 values, stride 136 (pad 8) + 64-word zero chunk.
// stride 136 mod 32 = 8 -> fragment gathers (8*c4 + r4) hit all 32 banks.
#define XSTR   136
#define XWORDS (XSTR * 64 + 64)          // 8768 floats
#define BANDW  10240                     // 8 m-tiles x 16 rows x 80 cols fp32
#define DSMEM_BYTES (BANDW * 4)          // 40960 >= XWORDS*4 (35072)

__device__ __forceinline__ uint32_t tf32r(float x) {
    uint32_t r;
    asm("cvt.rna.tf32.f32 %0, %1;" : "=r"(r) : "f"(x));
    return r;
}
__device__ __forceinline__ void mma_tf32(float* c, uint32_t a0, uint32_t a1,
                                         uint32_t a2, uint32_t a3,
                                         uint32_t b0, uint32_t b1) {
    asm volatile(
        "mma.sync.aligned.m16n8k8.row.col.f32.tf32.tf32.f32 "
        "{%0,%1,%2,%3}, {%4,%5,%6,%7}, {%8,%9}, {%0,%1,%2,%3};"
        : "+f"(c[0]), "+f"(c[1]), "+f"(c[2]), "+f"(c[3])
        : "r"(a0), "r"(a1), "r"(a2), "r"(a3), "r"(b0), "r"(b1));
}

__global__ __launch_bounds__(128, 5)
void autocorr_mma_kernel(const float* __restrict__ X, float* __restrict__ out)
{
    extern __shared__ __align__(16) float dsm[];
    float* xb   = dsm;                   // tf32-rounded centered row
    float* band = dsm;                   // aliased AFTER mainloop completes
    const uint32_t* xu = reinterpret_cast<const uint32_t*>(dsm);

    __shared__ float wsum[4], wsq[4];
    __shared__ float stats[2];           // [0]=mean, [1]=1/var0
    __shared__ float part[2][64];        // phase-5 partials

    const int tid = threadIdx.x;         // 0..127
    const int wid = tid >> 5;            // 0..3
    const int lid = tid & 31;
    const int r4  = lid >> 2;            // fragment row index
    const int c4  = lid & 3;             // fragment k index
    const int b   = blockIdx.x;

    const float4* Xr = reinterpret_cast<const float4*>(X + (size_t)b * T_LEN);

    // ---------------- Phase 1 (pass A): stream row, mean & sumsq only -------
    float s = 0.f, q = 0.f;
#pragma unroll
    for (int r = 0; r < 16; ++r) {
        const float4 v = Xr[tid + r * 128];
        s += v.x + v.y + v.z + v.w;
        q += v.x * v.x + v.y * v.y + v.z * v.z + v.w * v.w;
    }
#pragma unroll
    for (int o = 16; o > 0; o >>= 1) {
        s += __shfl_xor_sync(0xffffffffu, s, o);
        q += __shfl_xor_sync(0xffffffffu, q, o);
    }
    if (lid == 0) { wsum[wid] = s; wsq[wid] = q; }
    __syncthreads();
    if (tid == 0) {
        float S = wsum[0] + wsum[1] + wsum[2] + wsum[3];
        float Q = wsq[0] + wsq[1] + wsq[2] + wsq[3];
        float mean = S * (1.f / (float)T_LEN);
        stats[0] = mean;
        stats[1] = 1.f / (Q - (float)T_LEN * mean * mean);  // 1/T cancels in ratio
    }
    __syncthreads();
    const float mean = stats[0];

    // ---------------- Phase 2 (pass B): re-read (L2-hot), center, tf32 ------
#pragma unroll
    for (int r = 0; r < 16; ++r) {
        const float4 v = Xr[tid + r * 128];
        const int t0 = (tid + r * 128) * 4;
        const int ad = XSTR * (t0 >> 7) + (t0 & 127);   // 4 elems same chunk
        uint4 c;
        c.x = tf32r(v.x - mean);
        c.y = tf32r(v.y - mean);
        c.z = tf32r(v.z - mean);
        c.w = tf32r(v.w - mean);
        *reinterpret_cast<uint4*>(&xb[ad]) = c;
    }
    if (tid < NLAG) xb[XSTR * 64 + tid] = 0.f;          // zero chunk (t >= T)
    __syncthreads();

    // ---------------- Phase 3: band GEMM, 2 m-tiles per warp, full k --------
    // warp w: m-tiles {2w, 2w+1} (rows 32w..32w+31). B positions
    // u0 = 32w + 8j (j=0..11) serve both tiles; A-fragments for both tiles
    // ARE B pairs j=0..3 (u0 <= 120 < 128, never bumped). j>=4 loaded on the
    // fly to keep live registers under the 5-CTA cap.
    float C0[10][4], C1[10][4];
#pragma unroll
    for (int t = 0; t < 10; ++t)
#pragma unroll
        for (int j = 0; j < 4; ++j) { C0[t][j] = 0.f; C1[t][j] = 0.f; }

#pragma unroll 1
    for (int ks = 0; ks < 8; ++ks) {
        const int rowA = XSTR * (8 * ks + c4);
        const int rowB = rowA + XSTR * 4;
        const int ub0  = 32 * wid + r4;

        uint32_t p0[4], p1[4];
#pragma unroll
        for (int j = 0; j < 4; ++j) {        // u0 <= 120: no bump ever
            p0[j] = xu[rowA + ub0 + 8 * j];
            p1[j] = xu[rowB + ub0 + 8 * j];
        }

#pragma unroll
        for (int j = 0; j < 12; ++j) {
            uint32_t b0, b1;
            if (j < 4) { b0 = p0[j]; b1 = p1[j]; }
            else {
                const int u0 = 32 * wid + 8 * j;
                const int ub = u0 + ((u0 >= 128) ? 8 : 0) + r4;  // chunk bump
                b0 = xu[rowA + ub];
                b1 = xu[rowB + ub];
            }
            if (j < 10)
                mma_tf32(C0[j], p0[0], p0[1], p1[0], p1[1], b0, b1);
            if (j >= 2)
                mma_tf32(C1[j - 2], p0[2], p0[3], p1[2], p1[3], b0, b1);
        }
    }
    __syncthreads();   // all warps done reading xbuf; band may now alias it

    // ---------------- Phase 4: C fragments -> band (exclusive, no RMW) ------
    {
        float* bp0 = band + (2 * wid)     * 1280;
        float* bp1 = band + (2 * wid + 1) * 1280;
#pragma unroll
        for (int t = 0; t < 10; ++t) {
            const int cb = 8 * t + 2 * c4;
            *reinterpret_cast<float2*>(&bp0[r4 * 80 + cb])       = make_float2(C0[t][0], C0[t][1]);
            *reinterpret_cast<float2*>(&bp0[(r4 + 8) * 80 + cb]) = make_float2(C0[t][2], C0[t][3]);
            *reinterpret_cast<float2*>(&bp1[r4 * 80 + cb])       = make_float2(C1[t][0], C1[t][1]);
            *reinterpret_cast<float2*>(&bp1[(r4 + 8) * 80 + cb]) = make_float2(C1[t][2], C1[t][3]);
        }
    }
    __syncthreads();

    // ---------------- Phase 5: diagonal reduce + normalize + store ----------
    {
        const int h = tid >> 6;            // half: m-tiles 4h..4h+3
        const int k = (tid & 63) + 1;
        float acc = 0.f;
#pragma unroll
        for (int m = 0; m < 4; ++m) {
            const float* bp = band + (4 * h + m) * 1280;
            float ps = 0.f;
#pragma unroll
            for (int r = 0; r < 16; ++r)
                ps += bp[r * 80 + r + k];   // local col - row = lag
            acc += ps;
        }
        part[h][k - 1] = acc;
    }
    __syncthreads();
    if (tid < NLAG)
        out[(size_t)b * NLAG + tid] = (part[0][tid] + part[1][tid]) * stats[1];
}

extern "C" void kernel_launch(void* const* d_in, const int* in_sizes, int n_in,
                              void* d_out, int out_size)
{
    const float* X = (const float*)d_in[0];
    float* out = (float*)d_out;
    const int B = in_sizes[0] / T_LEN;   // 4096

    autocorr_mma_kernel<<<B, 128, DSMEM_BYTES>>>(X, out);
}

// round 15
// speedup vs baseline: 1.3705x; 1.3705x over previous
#include <cuda_runtime.h>
#include <cstdint>

#define T_LEN 8192
#define NLAG  64

// x buffer: 64 chunks of 128 values, stride 136 (pad 8) + 64-word zero chunk.
// stride 136 mod 32 = 8 -> fragment gathers (8*c4 + r4) hit all 32 banks.
#define XSTR   136
#define XWORDS (XSTR * 64 + 64)          // 8768 floats
#define BANDW  10240                     // 8 m-tiles x 16 rows x 80 cols fp32
#define DSMEM_BYTES (BANDW * 4)          // 40960 >= XWORDS*4 (35072)

__device__ __forceinline__ uint32_t tf32r(float x) {
    uint32_t r;
    asm("cvt.rna.tf32.f32 %0, %1;" : "=r"(r) : "f"(x));
    return r;
}
__device__ __forceinline__ void mma_tf32(float* c, uint32_t a0, uint32_t a1,
                                         uint32_t a2, uint32_t a3,
                                         uint32_t b0, uint32_t b1) {
    asm volatile(
        "mma.sync.aligned.m16n8k8.row.col.f32.tf32.tf32.f32 "
        "{%0,%1,%2,%3}, {%4,%5,%6,%7}, {%8,%9}, {%0,%1,%2,%3};"
        : "+f"(c[0]), "+f"(c[1]), "+f"(c[2]), "+f"(c[3])
        : "r"(a0), "r"(a1), "r"(a2), "r"(a3), "r"(b0), "r"(b1));
}

// One k-step: all shared-load offsets are immediates ([Rj + imm], zero ALU).
// rowA byte offset = 4*1088*KS (k row = 8*KS + c4, folded into ad[]);
// rowB = rowA + 4*544 (four chunks further).
template<int KS>
__device__ __forceinline__ void ks_step(const uint32_t* __restrict__ ad,
                                        float (*C0)[4], float (*C1)[4])
{
    uint32_t b0[12], b1[12];
#pragma unroll
    for (int j = 0; j < 12; ++j) {
        asm volatile("ld.shared.b32 %0, [%1+%2];"
                     : "=r"(b0[j]) : "r"(ad[j]), "n"(4 * 1088 * KS));
        asm volatile("ld.shared.b32 %0, [%1+%2];"
                     : "=r"(b1[j]) : "r"(ad[j]), "n"(4 * (1088 * KS + 544)));
    }
    // A-fragments for the warp's two m-tiles ARE b-pairs j=0..3 (A == B).
#pragma unroll
    for (int j = 0; j < 12; ++j) {
        if (j < 10)
            mma_tf32(C0[j],     b0[0], b0[1], b1[0], b1[1], b0[j], b1[j]);
        if (j >= 2)
            mma_tf32(C1[j - 2], b0[2], b0[3], b1[2], b1[3], b0[j], b1[j]);
    }
}

__global__ __launch_bounds__(128, 4)
void autocorr_mma_kernel(const float* __restrict__ X, float* __restrict__ out)
{
    extern __shared__ __align__(16) float dsm[];
    float* xb   = dsm;                   // tf32-rounded centered row
    float* band = dsm;                   // aliased AFTER mainloop completes
    const uint32_t* xu = reinterpret_cast<const uint32_t*>(dsm);

    __shared__ float wsum[4], wsq[4];
    __shared__ float stats[2];           // [0]=mean, [1]=1/var0
    __shared__ float part[2][64];        // phase-5 partials

    const int tid = threadIdx.x;         // 0..127
    const int wid = tid >> 5;            // 0..3
    const int lid = tid & 31;
    const int r4  = lid >> 2;            // fragment row index
    const int c4  = lid & 3;             // fragment k index
    const int b   = blockIdx.x;

    const float4* Xr = reinterpret_cast<const float4*>(X + (size_t)b * T_LEN);

    // ---------------- Phase 1: load row, mean & sumsq (exact fp32) ----------
    float4 xv[16];
    float s = 0.f, q = 0.f;
#pragma unroll
    for (int r = 0; r < 16; ++r) {
        xv[r] = Xr[tid + r * 128];
        s += xv[r].x + xv[r].y + xv[r].z + xv[r].w;
        q += xv[r].x * xv[r].x + xv[r].y * xv[r].y
           + xv[r].z * xv[r].z + xv[r].w * xv[r].w;
    }
#pragma unroll
    for (int o = 16; o > 0; o >>= 1) {
        s += __shfl_xor_sync(0xffffffffu, s, o);
        q += __shfl_xor_sync(0xffffffffu, q, o);
    }
    if (lid == 0) { wsum[wid] = s; wsq[wid] = q; }
    __syncthreads();
    if (tid == 0) {
        float S = wsum[0] + wsum[1] + wsum[2] + wsum[3];
        float Q = wsq[0] + wsq[1] + wsq[2] + wsq[3];
        float mean = S * (1.f / (float)T_LEN);
        stats[0] = mean;
        stats[1] = 1.f / (Q - (float)T_LEN * mean * mean);  // 1/T cancels in ratio
    }
    __syncthreads();
    const float mean = stats[0];

    // ---------------- Phase 2: centered tf32 values -> padded xbuf ----------
#pragma unroll
    for (int r = 0; r < 16; ++r) {
        const int t0 = (tid + r * 128) * 4;
        const int ad = XSTR * (t0 >> 7) + (t0 & 127);   // 4 elems same chunk
        uint4 c;
        c.x = tf32r(xv[r].x - mean);
        c.y = tf32r(xv[r].y - mean);
        c.z = tf32r(xv[r].z - mean);
        c.w = tf32r(xv[r].w - mean);
        *reinterpret_cast<uint4*>(&xb[ad]) = c;
    }
    if (tid < NLAG) xb[XSTR * 64 + tid] = 0.f;          // zero chunk (t >= T)
    __syncthreads();

    // ---------------- Phase 3: band GEMM, 2 m-tiles/warp, imm-offset LDS ----
    // warp w: m-tiles {2w, 2w+1}. B positions u0 = 32w + 8j (j=0..11);
    // per-thread smem byte addresses precomputed once (bump folded in).
    uint32_t adr[12];
    {
        uint32_t sbase;
        asm("{ .reg .u64 t; cvta.to.shared.u64 t, %1; cvt.u32.u64 %0, t; }"
            : "=r"(sbase) : "l"(dsm));
#pragma unroll
        for (int j = 0; j < 12; ++j) {
            const int u0 = 32 * wid + 8 * j;
            adr[j] = sbase + 4u * (uint32_t)(136 * c4 + u0
                                             + ((u0 >= 128) ? 8 : 0) + r4);
        }
    }

    float C0[10][4], C1[10][4];
#pragma unroll
    for (int t = 0; t < 10; ++t)
#pragma unroll
        for (int j = 0; j < 4; ++j) { C0[t][j] = 0.f; C1[t][j] = 0.f; }

    ks_step<0>(adr, C0, C1);
    ks_step<1>(adr, C0, C1);
    ks_step<2>(adr, C0, C1);
    ks_step<3>(adr, C0, C1);
    ks_step<4>(adr, C0, C1);
    ks_step<5>(adr, C0, C1);
    ks_step<6>(adr, C0, C1);
    ks_step<7>(adr, C0, C1);

    __syncthreads();   // all warps done reading xbuf; band may now alias it

    // ---------------- Phase 4: C fragments -> band (exclusive, no RMW) ------
    {
        float* bp0 = band + (2 * wid)     * 1280;
        float* bp1 = band + (2 * wid + 1) * 1280;
#pragma unroll
        for (int t = 0; t < 10; ++t) {
            const int cb = 8 * t + 2 * c4;
            *reinterpret_cast<float2*>(&bp0[r4 * 80 + cb])       = make_float2(C0[t][0], C0[t][1]);
            *reinterpret_cast<float2*>(&bp0[(r4 + 8) * 80 + cb]) = make_float2(C0[t][2], C0[t][3]);
            *reinterpret_cast<float2*>(&bp1[r4 * 80 + cb])       = make_float2(C1[t][0], C1[t][1]);
            *reinterpret_cast<float2*>(&bp1[(r4 + 8) * 80 + cb]) = make_float2(C1[t][2], C1[t][3]);
        }
    }
    __syncthreads();

    // ---------------- Phase 5: diagonal reduce + normalize + store ----------
    {
        const int h = tid >> 6;            // half: m-tiles 4h..4h+3
        const int k = (tid & 63) + 1;
        float acc = 0.f;
#pragma unroll
        for (int m = 0; m < 4; ++m) {
            const float* bp = band + (4 * h + m) * 1280;
            float ps = 0.f;
#pragma unroll
            for (int r = 0; r < 16; ++r)
                ps += bp[r * 80 + r + k];   // local col - row = lag
            acc += ps;
        }
        part[h][k - 1] = acc;
    }
    __syncthreads();
    if (tid < NLAG)
        out[(size_t)b * NLAG + tid] = (part[0][tid] + part[1][tid]) * stats[1];
}

extern "C" void kernel_launch(void* const* d_in, const int* in_sizes, int n_in,
                              void* d_out, int out_size)
{
    const float* X = (const float*)d_in[0];
    float* out = (float*)d_out;
    const int B = in_sizes[0] / T_LEN;   // 4096

    autocorr_mma_kernel<<<B, 128, DSMEM_BYTES>>>(X, out);
}